// round 7
// baseline (speedup 1.0000x reference)
#include <cuda_runtime.h>
#include <cstdint>

#define B_ 16
#define T_ 2048
#define D_ 256
#define C_ 8
#define TILE 32
#define NCHUNKS (T_ / TILE)      // 64
#define NBLOCKS (B_ * NCHUNKS)   // 1024

typedef unsigned long long ull;
union f4u { float4 v; ull u[2]; };

__device__ __forceinline__ ull ffma2(ull a, ull b, ull c) {
    ull d;
    asm("fma.rn.f32x2 %0, %1, %2, %3;" : "=l"(d) : "l"(a), "l"(b), "l"(c));
    return d;
}
__device__ __forceinline__ ull add2(ull a, ull b) {
    ull d;
    asm("add.rn.f32x2 %0, %1, %2;" : "=l"(d) : "l"(a), "l"(b));
    return d;
}
__device__ __forceinline__ float2 upk(ull v) {
    float2 r;
    asm("mov.b64 {%0, %1}, %2;" : "=f"(r.x), "=f"(r.y) : "l"(v));
    return r;
}
__device__ __forceinline__ ull pk2(float lo, float hi) {
    ull r;
    asm("mov.b64 %0, {%1, %2};" : "=l"(r) : "f"(lo), "f"(hi));
    return r;
}
__device__ __forceinline__ void cp16(uint32_t saddr, const void* g) {
    asm volatile("cp.async.cg.shared.global [%0], [%1], 16;" :: "r"(saddr), "l"(g));
}
#define CP_COMMIT() asm volatile("cp.async.commit_group;")
#define CP_WAIT0()  asm volatile("cp.async.wait_group 0;")

__global__ void lde_zero_kernel(float* __restrict__ out, int n) {
    int i = blockIdx.x * blockDim.x + threadIdx.x;
    if (i < n) out[i] = 0.0f;
}

__global__ void __launch_bounds__(256, 3) lde_main_kernel(
    const float* __restrict__ x,        // (B,T,D)
    const float* __restrict__ centers,  // (C,D)
    const float* __restrict__ scale,    // (C,)
    float* __restrict__ out)            // (B, C*D)
{
    __shared__ float4 xbuf[TILE * 64];   // 32 KB, swizzled slot = d4 ^ t
    __shared__ float4 ct[64 * C_];       // 8 KB: [d4][c]
    __shared__ float  logit[TILE * 9];   // per token: 8 dots + xsq
    __shared__ float  a_s[TILE * C_];    // plain softmax weights
    __shared__ ull    scratch[8 * 128];  // 8 KB: [slice][h] combine buffer
    __shared__ float  asum_s[C_];
    __shared__ float  csq_s[C_];
    __shared__ float  scl_s[C_];

    const int tid  = threadIdx.x;
    const int w    = tid >> 5;
    const int lane = tid & 31;
    const int b     = blockIdx.x >> 6;        // / NCHUNKS
    const int chunk = blockIdx.x & (NCHUNKS - 1);

    // ---- 1) kick off x tile load (32 KB) ----
    const float4* gx4 = (const float4*)(x + ((size_t)b * T_ + chunk * TILE) * D_);
    const uint32_t xs_base = (uint32_t)__cvta_generic_to_shared(xbuf);
#pragma unroll
    for (int j = 0; j < 8; j++) {
        int i = tid + j * 256;                // 0..2047
        int t = i >> 6, d4 = i & 63;
        cp16(xs_base + (uint32_t)((t * 64 + (d4 ^ t)) * 16), gx4 + i);
    }
    CP_COMMIT();

    // ---- 2) init (overlaps cp.async flight) ----
    for (int i = tid; i < TILE * 9; i += 256) logit[i] = 0.0f;
    if (tid < C_) { asum_s[tid] = 0.0f; scl_s[tid] = scale[tid]; }
    for (int i = tid; i < C_ * D_; i += 256) {
        int c = i >> 8, d = i & 255;
        ((float*)ct)[((d >> 2) * C_ + c) * 4 + (d & 3)] = centers[i];
    }
    // csq: warp w handles cluster w (from global, overlaps)
    {
        float s = 0.0f;
#pragma unroll
        for (int j = 0; j < 8; j++) {
            float v = centers[w * D_ + lane + 32 * j];
            s = fmaf(v, v, s);
        }
#pragma unroll
        for (int o = 16; o; o >>= 1) s += __shfl_xor_sync(0xffffffffu, s, o);
        if (lane == 0) csq_s[w] = s;
    }

    CP_WAIT0();
    __syncthreads();   // barrier #1

    // ---- 3) phase A: lane = token, warp w covers d4 in [8w, 8w+8) ----
    {
        ull red[9];
#pragma unroll
        for (int j = 0; j < 9; j++) red[j] = 0ULL;
#pragma unroll
        for (int i = 0; i < 8; i++) {
            const int d4 = w * 8 + i;
            f4u xv; xv.v = xbuf[lane * 64 + (d4 ^ lane)];
#pragma unroll
            for (int c = 0; c < C_; c++) {
                f4u cv; cv.v = ct[d4 * C_ + c];
                red[c] = ffma2(xv.u[0], cv.u[0], ffma2(xv.u[1], cv.u[1], red[c]));
            }
            red[8] = ffma2(xv.u[0], xv.u[0], ffma2(xv.u[1], xv.u[1], red[8]));
        }
#pragma unroll
        for (int j = 0; j < 9; j++) {
            float2 p = upk(red[j]);
            atomicAdd(&logit[lane * 9 + j], p.x + p.y);
        }
    }
    __syncthreads();   // barrier #2

    // ---- 4) softmax: thread (t = tid/8, c = tid%8) ----
    {
        const int t = tid >> 3, c = tid & 7;
        const float dot = logit[t * 9 + c];
        const float xsq = logit[t * 9 + 8];
        float lg = scl_s[c] * (2.0f * dot - xsq - csq_s[c]);
        float m = lg;
        m = fmaxf(m, __shfl_xor_sync(0xffffffffu, m, 1));
        m = fmaxf(m, __shfl_xor_sync(0xffffffffu, m, 2));
        m = fmaxf(m, __shfl_xor_sync(0xffffffffu, m, 4));
        const float e = __expf(lg - m);
        float sd = e;
        sd += __shfl_xor_sync(0xffffffffu, sd, 1);
        sd += __shfl_xor_sync(0xffffffffu, sd, 2);
        sd += __shfl_xor_sync(0xffffffffu, sd, 4);
        const float a = e / sd;
        a_s[t * 8 + c] = a;
        float r = a;
        r += __shfl_xor_sync(0xffffffffu, r, 8);
        r += __shfl_xor_sync(0xffffffffu, r, 16);
        if (lane < 8) atomicAdd(&asum_s[lane], r);   // 8 addrs, tiny
    }
    __syncthreads();   // barrier #3

    // ---- 5) phase B: thread h owns dims {2h, 2h+1}; half-block token split ----
    // acc2[j*2+dd] = pair (acc[c=2j][d_dd], acc[c=2j+1][d_dd])
    const int h     = tid & 127;
    const int uhalf = tid >> 7;          // 0: tokens 0-15, 1: tokens 16-31
    const int d4l   = h >> 1;            // float4 slot of this thread's dims
    const int off   = (h & 1) * 2;       // word offset within the float4

    ull acc2[8];
#pragma unroll
    for (int j = 0; j < 8; j++) acc2[j] = 0ULL;
    {
        const float* xbf = (const float*)xbuf;
        const int tb = uhalf * 16;
#pragma unroll 4
        for (int t = 0; t < 16; t++) {
            const int tt = tb + t;
            const ull xp = *(const ull*)(xbf + (tt * 64 + (d4l ^ tt)) * 4 + off);
            const float2 xv = upk(xp);
            const ull xd0 = pk2(xv.x, xv.x);
            const ull xd1 = pk2(xv.y, xv.y);
            f4u a0; a0.v = *(const float4*)&a_s[tt * 8];      // (a0,a1),(a2,a3)
            f4u a1; a1.v = *(const float4*)&a_s[tt * 8 + 4];  // (a4,a5),(a6,a7)
            acc2[0] = ffma2(a0.u[0], xd0, acc2[0]);
            acc2[1] = ffma2(a0.u[0], xd1, acc2[1]);
            acc2[2] = ffma2(a0.u[1], xd0, acc2[2]);
            acc2[3] = ffma2(a0.u[1], xd1, acc2[3]);
            acc2[4] = ffma2(a1.u[0], xd0, acc2[4]);
            acc2[5] = ffma2(a1.u[0], xd1, acc2[5]);
            acc2[6] = ffma2(a1.u[1], xd0, acc2[6]);
            acc2[7] = ffma2(a1.u[1], xd1, acc2[7]);
        }
    }

    // upper half publishes its partials
    if (uhalf) {
#pragma unroll
        for (int j = 0; j < 8; j++) scratch[j * 128 + h] = acc2[j];
    }
    __syncthreads();   // barrier #4

    // ---- 6) lower half combines + epilogue ----
    if (!uhalf) {
#pragma unroll
        for (int j = 0; j < 8; j++) acc2[j] = add2(acc2[j], scratch[j * 128 + h]);

        const float* ctf = (const float*)ct;
        float* ob = out + b * (C_ * D_);
        float as[C_];
#pragma unroll
        for (int c = 0; c < C_; c++) as[c] = asum_s[c];
        const int d0 = 2 * h, d1 = 2 * h + 1;
#pragma unroll
        for (int j = 0; j < 4; j++) {
            const int c0 = 2 * j, c1 = 2 * j + 1;
            const float2 p0 = upk(acc2[j * 2]);      // (acc[c0][d0], acc[c1][d0])
            const float2 p1 = upk(acc2[j * 2 + 1]);  // (acc[c0][d1], acc[c1][d1])
            const float cv00 = ctf[(d4l * C_ + c0) * 4 + off];
            const float cv01 = ctf[(d4l * C_ + c0) * 4 + off + 1];
            const float cv10 = ctf[(d4l * C_ + c1) * 4 + off];
            const float cv11 = ctf[(d4l * C_ + c1) * 4 + off + 1];
            atomicAdd(ob + c0 * 256 + d0, p0.x - as[c0] * cv00);
            atomicAdd(ob + c0 * 256 + d1, p1.x - as[c0] * cv01);
            atomicAdd(ob + c1 * 256 + d0, p0.y - as[c1] * cv10);
            atomicAdd(ob + c1 * 256 + d1, p1.y - as[c1] * cv11);
        }
    }
}

extern "C" void kernel_launch(void* const* d_in, const int* in_sizes, int n_in,
                              void* d_out, int out_size) {
    const float* x       = (const float*)d_in[0];
    const float* centers = (const float*)d_in[1];
    const float* scale   = (const float*)d_in[2];
    float* out           = (float*)d_out;
    (void)in_sizes; (void)n_in;

    lde_zero_kernel<<<(out_size + 255) / 256, 256>>>(out, out_size);
    lde_main_kernel<<<NBLOCKS, 256>>>(x, centers, scale, out);
}

// round 8
// speedup vs baseline: 1.1444x; 1.1444x over previous
#include <cuda_runtime.h>
#include <cstdint>

#define B_ 16
#define T_ 2048
#define D_ 256
#define C_ 8
#define TILE 32
#define NCHUNKS (T_ / TILE)      // 64
#define NBLOCKS (B_ * NCHUNKS)   // 1024
#define NTHREADS 128

typedef unsigned long long ull;
union f4u { float4 v; ull u[2]; };

__device__ __forceinline__ ull ffma2(ull a, ull b, ull c) {
    ull d;
    asm("fma.rn.f32x2 %0, %1, %2, %3;" : "=l"(d) : "l"(a), "l"(b), "l"(c));
    return d;
}
__device__ __forceinline__ float2 upk(ull v) {
    float2 r;
    asm("mov.b64 {%0, %1}, %2;" : "=f"(r.x), "=f"(r.y) : "l"(v));
    return r;
}
__device__ __forceinline__ ull pk2(float lo, float hi) {
    ull r;
    asm("mov.b64 %0, {%1, %2};" : "=l"(r) : "f"(lo), "f"(hi));
    return r;
}
__device__ __forceinline__ void cp16(uint32_t saddr, const void* g) {
    asm volatile("cp.async.cg.shared.global [%0], [%1], 16;" :: "r"(saddr), "l"(g));
}
#define CP_COMMIT() asm volatile("cp.async.commit_group;")
#define CP_WAIT0()  asm volatile("cp.async.wait_group 0;")

__global__ void lde_zero_kernel(float* __restrict__ out, int n) {
    int i = blockIdx.x * blockDim.x + threadIdx.x;
    if (i < n) out[i] = 0.0f;
}

__global__ void __launch_bounds__(NTHREADS, 5) lde_main_kernel(
    const float* __restrict__ x,        // (B,T,D)
    const float* __restrict__ centers,  // (C,D)
    const float* __restrict__ scale,    // (C,)
    float* __restrict__ out)            // (B, C*D)
{
    __shared__ float4 xbuf[TILE * 64];   // 32 KB, swizzled slot = d4 ^ t
    __shared__ float4 ct[64 * C_];       // 8 KB: [d4][c]
    __shared__ float  logit[TILE * 9];   // per token: 8 dots + xsq
    __shared__ float  a_s[TILE * C_];    // softmax weights
    __shared__ float  asum_s[C_];
    __shared__ float  csq_s[C_];
    __shared__ float  scl_s[C_];

    const int tid  = threadIdx.x;
    const int w    = tid >> 5;           // 0..3
    const int lane = tid & 31;
    const int b     = blockIdx.x >> 6;        // / NCHUNKS
    const int chunk = blockIdx.x & (NCHUNKS - 1);

    // ---- 1) kick off x tile load (32 KB), 16 cp.async per thread ----
    const float4* gx4 = (const float4*)(x + ((size_t)b * T_ + chunk * TILE) * D_);
    const uint32_t xs_base = (uint32_t)__cvta_generic_to_shared(xbuf);
#pragma unroll
    for (int j = 0; j < 16; j++) {
        int i = tid + j * NTHREADS;           // 0..2047
        int t = i >> 6, d4 = i & 63;
        cp16(xs_base + (uint32_t)((t * 64 + (d4 ^ t)) * 16), gx4 + i);
    }
    CP_COMMIT();

    // ---- 2) init (overlaps cp.async flight) ----
    for (int i = tid; i < TILE * 9; i += NTHREADS) logit[i] = 0.0f;
    if (tid < C_) { asum_s[tid] = 0.0f; scl_s[tid] = scale[tid]; }
    for (int i = tid; i < C_ * D_; i += NTHREADS) {
        int c = i >> 8, d = i & 255;
        ((float*)ct)[((d >> 2) * C_ + c) * 4 + (d & 3)] = centers[i];
    }
    // csq: warp w handles clusters 2w and 2w+1
    {
        float s0 = 0.0f, s1 = 0.0f;
#pragma unroll
        for (int j = 0; j < 8; j++) {
            float v0 = centers[(2 * w) * D_ + lane + 32 * j];
            float v1 = centers[(2 * w + 1) * D_ + lane + 32 * j];
            s0 = fmaf(v0, v0, s0);
            s1 = fmaf(v1, v1, s1);
        }
#pragma unroll
        for (int o = 16; o; o >>= 1) {
            s0 += __shfl_xor_sync(0xffffffffu, s0, o);
            s1 += __shfl_xor_sync(0xffffffffu, s1, o);
        }
        if (lane == 0) { csq_s[2 * w] = s0; csq_s[2 * w + 1] = s1; }
    }

    CP_WAIT0();
    __syncthreads();   // barrier #1

    // ---- 3) phase A: lane = token, warp w covers d4 in [16w, 16w+16) ----
    {
        ull red[9];
#pragma unroll
        for (int j = 0; j < 9; j++) red[j] = 0ULL;
#pragma unroll
        for (int i = 0; i < 16; i++) {
            const int d4 = w * 16 + i;
            f4u xv; xv.v = xbuf[lane * 64 + (d4 ^ lane)];
#pragma unroll
            for (int c = 0; c < C_; c++) {
                f4u cv; cv.v = ct[d4 * C_ + c];
                red[c] = ffma2(xv.u[0], cv.u[0], ffma2(xv.u[1], cv.u[1], red[c]));
            }
            red[8] = ffma2(xv.u[0], xv.u[0], ffma2(xv.u[1], xv.u[1], red[8]));
        }
#pragma unroll
        for (int j = 0; j < 9; j++) {
            float2 p = upk(red[j]);
            atomicAdd(&logit[lane * 9 + j], p.x + p.y);   // 4-way combine now
        }
    }
    __syncthreads();   // barrier #2

    // ---- 4) softmax: thread = (t = tid/4, cluster pair q = tid%4) ----
    {
        const int t  = tid >> 2;
        const int q  = tid & 3;
        const int c0 = 2 * q, c1 = 2 * q + 1;
        const float dot0 = logit[t * 9 + c0];
        const float dot1 = logit[t * 9 + c1];
        const float xsq  = logit[t * 9 + 8];
        float lg0 = scl_s[c0] * (2.0f * dot0 - xsq - csq_s[c0]);
        float lg1 = scl_s[c1] * (2.0f * dot1 - xsq - csq_s[c1]);
        float m = fmaxf(lg0, lg1);
        m = fmaxf(m, __shfl_xor_sync(0xffffffffu, m, 1));
        m = fmaxf(m, __shfl_xor_sync(0xffffffffu, m, 2));
        const float e0 = __expf(lg0 - m);
        const float e1 = __expf(lg1 - m);
        float sd = e0 + e1;
        sd += __shfl_xor_sync(0xffffffffu, sd, 1);
        sd += __shfl_xor_sync(0xffffffffu, sd, 2);
        const float inv = 1.0f / sd;
        const float a0 = e0 * inv, a1 = e1 * inv;
        *(float2*)&a_s[t * 8 + c0] = make_float2(a0, a1);   // STS.64
        // per-cluster partial sums over this warp's 8 tokens
        float r0 = a0, r1 = a1;
        r0 += __shfl_xor_sync(0xffffffffu, r0, 4);
        r1 += __shfl_xor_sync(0xffffffffu, r1, 4);
        r0 += __shfl_xor_sync(0xffffffffu, r0, 8);
        r1 += __shfl_xor_sync(0xffffffffu, r1, 8);
        r0 += __shfl_xor_sync(0xffffffffu, r0, 16);
        r1 += __shfl_xor_sync(0xffffffffu, r1, 16);
        if (lane < 4) {
            atomicAdd(&asum_s[c0], r0);
            atomicAdd(&asum_s[c1], r1);
        }
    }
    __syncthreads();   // barrier #3

    // ---- 5) phase B: thread tid owns dims {2*tid, 2*tid+1}, all 32 tokens ----
    const int d4l = tid >> 1;            // float4 slot of this thread's dims
    const int off = (tid & 1) * 2;       // word offset within the float4

    ull acc2[8];                         // acc2[j*2+dd] = (acc[2j][d_dd], acc[2j+1][d_dd])
#pragma unroll
    for (int j = 0; j < 8; j++) acc2[j] = 0ULL;
    {
        const float* xbf = (const float*)xbuf;
#pragma unroll 4
        for (int t = 0; t < TILE; t++) {
            const ull xp = *(const ull*)(xbf + (t * 64 + (d4l ^ t)) * 4 + off);
            const float2 xv = upk(xp);
            const ull xd0 = pk2(xv.x, xv.x);
            const ull xd1 = pk2(xv.y, xv.y);
            f4u a0; a0.v = *(const float4*)&a_s[t * 8];      // (a0,a1),(a2,a3)
            f4u a1; a1.v = *(const float4*)&a_s[t * 8 + 4];  // (a4,a5),(a6,a7)
            acc2[0] = ffma2(a0.u[0], xd0, acc2[0]);
            acc2[1] = ffma2(a0.u[0], xd1, acc2[1]);
            acc2[2] = ffma2(a0.u[1], xd0, acc2[2]);
            acc2[3] = ffma2(a0.u[1], xd1, acc2[3]);
            acc2[4] = ffma2(a1.u[0], xd0, acc2[4]);
            acc2[5] = ffma2(a1.u[0], xd1, acc2[5]);
            acc2[6] = ffma2(a1.u[1], xd0, acc2[6]);
            acc2[7] = ffma2(a1.u[1], xd1, acc2[7]);
        }
    }

    // ---- 6) epilogue: atomic accumulate into out ----
    {
        const float* ctf = (const float*)ct;
        float* ob = out + b * (C_ * D_);
        float as[C_];
#pragma unroll
        for (int c = 0; c < C_; c++) as[c] = asum_s[c];
        const int d0 = 2 * tid, d1 = 2 * tid + 1;
#pragma unroll
        for (int j = 0; j < 4; j++) {
            const int c0 = 2 * j, c1 = 2 * j + 1;
            const float2 p0 = upk(acc2[j * 2]);      // (acc[c0][d0], acc[c1][d0])
            const float2 p1 = upk(acc2[j * 2 + 1]);  // (acc[c0][d1], acc[c1][d1])
            const float cv00 = ctf[(d4l * C_ + c0) * 4 + off];
            const float cv01 = ctf[(d4l * C_ + c0) * 4 + off + 1];
            const float cv10 = ctf[(d4l * C_ + c1) * 4 + off];
            const float cv11 = ctf[(d4l * C_ + c1) * 4 + off + 1];
            atomicAdd(ob + c0 * 256 + d0, p0.x - as[c0] * cv00);
            atomicAdd(ob + c0 * 256 + d1, p1.x - as[c0] * cv01);
            atomicAdd(ob + c1 * 256 + d0, p0.y - as[c1] * cv10);
            atomicAdd(ob + c1 * 256 + d1, p1.y - as[c1] * cv11);
        }
    }
}

extern "C" void kernel_launch(void* const* d_in, const int* in_sizes, int n_in,
                              void* d_out, int out_size) {
    const float* x       = (const float*)d_in[0];
    const float* centers = (const float*)d_in[1];
    const float* scale   = (const float*)d_in[2];
    float* out           = (float*)d_out;
    (void)in_sizes; (void)n_in;

    lde_zero_kernel<<<(out_size + 255) / 256, 256>>>(out, out_size);
    lde_main_kernel<<<NBLOCKS, NTHREADS>>>(x, centers, scale, out);
}